// round 12
// baseline (speedup 1.0000x reference)
#include <cuda_runtime.h>
#include <cstdint>

#define NUM_C   64
#define FD      128
#define FD4     32
#define BLK     256
#define NWARP   8
#define GRID    3552         // chunk = 282 rows = 144KB window; 592 resident windows ~ 85MB < L2
#define PER_CAP 288
#define GRP     4
#define CPW     (NUM_C / NWARP)
#define N_PAIRS 2016
#define SMEM_DYN (52 * 1024) // 32KB used (sacc/cent); padded to cap occupancy at 4 blocks/SM

__device__ float        g_sums[NUM_C * FD];
__device__ int          g_counts[NUM_C];
__device__ float        g_sumsq;
__device__ unsigned int g_ticket;

__global__ void __launch_bounds__(BLK)
fused_k(const float* __restrict__ feat, const int* __restrict__ tgt, int B,
        float* __restrict__ out)
{
    extern __shared__ __align__(16) float sacc[];    // [NUM_C*FD] accumulator / cent alias
    float4* sacc4 = (float4*)sacc;

    __shared__ unsigned int  scomb[PER_CAP];         // sorted: rowid | (class<<16)
    __shared__ unsigned char stgt[PER_CAP];
    __shared__ int   hist[NUM_C];
    __shared__ int   pref[NUM_C];
    __shared__ int   cur[NUM_C];
    __shared__ float s_red[NWARP], s_sq[NWARP], s_hred[NWARP];
    __shared__ int   s_last;

    const int tid = threadIdx.x;
    const int w = tid >> 5, l = tid & 31;

    const int per = (B + GRID - 1) / GRID;
    const int r0  = (int)((long long)blockIdx.x * per);
    int n = B - r0; if (n > per) n = per; if (n < 0) n = 0;

    // ---- phase 0: sequential toucher — computes sumsq AND installs window in L2 ----
    const float4* fw = (const float4*)feat + (size_t)r0 * FD4;
    const int tot4 = n * FD4;
    float sq0 = 0.f, sq1 = 0.f;
    int i = tid;
    for (; i + 3 * BLK < tot4; i += 4 * BLK) {       // 4 front-batched LDG.128, sequential
        float4 a = fw[i], b = fw[i + BLK], c = fw[i + 2 * BLK], d = fw[i + 3 * BLK];
        sq0 = fmaf(a.x, a.x, fmaf(a.y, a.y, fmaf(a.z, a.z, fmaf(a.w, a.w, sq0))));
        sq1 = fmaf(b.x, b.x, fmaf(b.y, b.y, fmaf(b.z, b.z, fmaf(b.w, b.w, sq1))));
        sq0 = fmaf(c.x, c.x, fmaf(c.y, c.y, fmaf(c.z, c.z, fmaf(c.w, c.w, sq0))));
        sq1 = fmaf(d.x, d.x, fmaf(d.y, d.y, fmaf(d.z, d.z, fmaf(d.w, d.w, sq1))));
    }
    for (; i < tot4; i += BLK) {
        float4 a = fw[i];
        sq0 = fmaf(a.x, a.x, fmaf(a.y, a.y, fmaf(a.z, a.z, fmaf(a.w, a.w, sq0))));
    }

    // zero accumulator + histogram
    for (int k = tid; k < NUM_C * FD4; k += BLK) sacc4[k] = make_float4(0.f, 0.f, 0.f, 0.f);
    if (tid < NUM_C) hist[tid] = 0;
    __syncthreads();

    // ---- phase A: load targets, histogram ----
    for (int k = tid; k < n; k += BLK) {
        int t = tgt[r0 + k];
        stgt[k] = (unsigned char)t;
        atomicAdd(&hist[t], 1);
    }
    __syncthreads();

    // ---- exclusive prefix over 64 counts (warp 0) ----
    if (w == 0) {
        int a = hist[l], b = hist[l + 32];
        int ia = a, ib = b;
#pragma unroll
        for (int o = 1; o < 32; o <<= 1) { int t = __shfl_up_sync(0xffffffffu, ia, o); if (l >= o) ia += t; }
#pragma unroll
        for (int o = 1; o < 32; o <<= 1) { int t = __shfl_up_sync(0xffffffffu, ib, o); if (l >= o) ib += t; }
        int totA = __shfl_sync(0xffffffffu, ia, 31);
        pref[l]      = ia - a;         cur[l]      = ia - a;
        pref[l + 32] = totA + ib - b;  cur[l + 32] = totA + ib - b;
    }
    __syncthreads();

    // ---- phase B: scatter (rowid | class<<16) into class-sorted order ----
    for (int k = tid; k < n; k += BLK) {
        int t = stgt[k];
        int pos = atomicAdd(&cur[t], 1);
        scomb[pos] = (unsigned int)k | ((unsigned int)t << 16);
    }
    __syncthreads();

    // ---- phase C: warp owns classes [8w,8w+8); gather (L2-hot) + register acc;
    //      flush = one plain STS.128 per class (exclusive ownership) ----
    const float4* fl = (const float4*)feat + l;
    const int p0 = pref[w * CPW];
    const int p1 = (w == NWARP - 1) ? n : pref[w * CPW + CPW];

    float4 acc = make_float4(0.f, 0.f, 0.f, 0.f);
    int ccur = (p0 < p1) ? (int)(scomb[p0] >> 16) : -1;

    int p = p0;
    for (; p + GRP <= p1; p += GRP) {
        unsigned int cb[GRP];
#pragma unroll
        for (int u = 0; u < GRP; u++) cb[u] = scomb[p + u];
        float4 v[GRP];
#pragma unroll
        for (int u = 0; u < GRP; u++)
            v[u] = fl[(size_t)(r0 + (cb[u] & 0xffffu)) * FD4];
#pragma unroll
        for (int u = 0; u < GRP; u++) {
            float4 x = v[u];
            int c = (int)(cb[u] >> 16);
            if (c != ccur) {
                sacc4[ccur * FD4 + l] = acc;          // plain STS.128 (exclusive)
                acc = make_float4(0.f, 0.f, 0.f, 0.f);
                ccur = c;
            }
            acc.x += x.x; acc.y += x.y; acc.z += x.z; acc.w += x.w;
        }
    }
    for (; p < p1; p++) {
        unsigned int cb = scomb[p];
        int c = (int)(cb >> 16);
        float4 x = fl[(size_t)(r0 + (cb & 0xffffu)) * FD4];
        if (c != ccur) {
            sacc4[ccur * FD4 + l] = acc;
            acc = make_float4(0.f, 0.f, 0.f, 0.f);
            ccur = c;
        }
        acc.x += x.x; acc.y += x.y; acc.z += x.z; acc.w += x.w;
    }
    if (p1 > p0) sacc4[ccur * FD4 + l] = acc;
    __syncthreads();

    // ---- block-end merge ----
    for (int k = tid; k < NUM_C * FD; k += BLK)
        atomicAdd(&g_sums[k], sacc[k]);
    if (tid < NUM_C) atomicAdd(&g_counts[tid], hist[tid]);

    float sq = sq0 + sq1;
#pragma unroll
    for (int o = 16; o > 0; o >>= 1) sq += __shfl_down_sync(0xffffffffu, sq, o);
    if (l == 0) s_sq[w] = sq;
    __syncthreads();
    if (tid == 0) {
        float t = 0.f;
#pragma unroll
        for (int k = 0; k < NWARP; k++) t += s_sq[k];
        atomicAdd(&g_sumsq, t);
    }

    __threadfence();
    __syncthreads();
    if (tid == 0) {
        unsigned int tk = atomicAdd(&g_ticket, 1u);
        s_last = (tk == gridDim.x - 1);
    }
    __syncthreads();
    if (!s_last) return;

    // ================= last block: epilogue (cent aliases sacc) =================
    __threadfence();
    float* cent = sacc;

    float ipart = 0.f;
    for (int k = tid; k < NUM_C * FD; k += BLK) {
        const int c = k >> 7;
        float cntc = fmaxf((float)g_counts[c], 1.0f);
        float s  = g_sums[k];
        float ce = s / cntc;
        cent[k]  = ce;
        ipart   += s * ce;                 // sum_c cnt_c * ||cent_c||^2
        g_sums[k] = 0.f;                   // reset for next graph replay
    }
    float ssq = 0.f;
    if (tid == 0) { ssq = g_sumsq; g_sumsq = 0.f; g_ticket = 0u; }
    __syncthreads();
    if (tid < NUM_C) g_counts[tid] = 0;

#pragma unroll
    for (int o = 16; o > 0; o >>= 1) ipart += __shfl_down_sync(0xffffffffu, ipart, o);
    if (l == 0) s_red[w] = ipart;
    __syncthreads();

    const float4* c4 = (const float4*)cent;
    float hsum = 0.f;
    for (int ii = w; ii < NUM_C - 1; ii += NWARP) {
        float4 a = c4[ii * FD4 + l];
        for (int j = ii + 1; j < NUM_C; j++) {
            float4 b = c4[j * FD4 + l];
            float dx = a.x - b.x, dy = a.y - b.y, dz = a.z - b.z, dw = a.w - b.w;
            float d2 = dx * dx + dy * dy + dz * dz + dw * dw;
#pragma unroll
            for (int o = 16; o > 0; o >>= 1) d2 += __shfl_down_sync(0xffffffffu, d2, o);
            if (l == 0) {
                float wt = (ii == 1 && j == 2) ? 2.0f : 1.0f;
                hsum += wt * fmaxf(2.0f - d2, 0.0f);     // MARGIN = 2
            }
        }
    }
    if (l == 0) s_hred[w] = hsum;
    __syncthreads();

    if (tid == 0) {
        float isum = 0.f, hs = 0.f;
#pragma unroll
        for (int k = 0; k < NWARP; k++) { isum += s_red[k]; hs += s_hred[k]; }
        out[0] = (ssq - isum) / (float)B + hs / (float)N_PAIRS;
    }
}

extern "C" void kernel_launch(void* const* d_in, const int* in_sizes, int n_in,
                              void* d_out, int out_size) {
    const float* feat = (const float*)d_in[0];
    const int*   tgt  = (const int*)d_in[1];
    const int B = in_sizes[1];
    cudaFuncSetAttribute(fused_k, cudaFuncAttributeMaxDynamicSharedMemorySize, SMEM_DYN);
    fused_k<<<GRID, BLK, SMEM_DYN>>>(feat, tgt, B, (float*)d_out);
}